// round 9
// baseline (speedup 1.0000x reference)
#include <cuda_runtime.h>

#define MAXN     102400
#define IN_FEATS 16
#define UNROLL   4

// Scratch (device globals — zero at module load; each pass re-zeros what it
// consumed so every kernel_launch call starts from the same state)
__device__ int    g_deg[MAXN];   // zeroed by k_norm after use
__device__ float  g_norm[MAXN];
__device__ float4 g_Us[MAXN];    // unscaled X0·[M1|M2], then scaled by k_norm
__device__ float2 g_XA[MAXN];    // X0·M0
__device__ float4 g_Vacc[MAXN];  // pass-1 acc (zeroed by k_out after use)
__device__ float2 g_Zs[MAXN];    // norm²-scaled M2-half of pass-1 result
__device__ float2 g_Tacc[MAXN];  // pass-2 acc (zeroed by k_out after use)
__device__ int    g_is64;

// --- detect int32 vs int64 indices (1 block) ---
__global__ void k_detect(const unsigned* __restrict__ w, int E) {
    __shared__ int s_any;
    if (threadIdx.x == 0) s_any = 0;
    __syncthreads();
    int limit = (E < 4096) ? E : 4096;
    for (int k = threadIdx.x; k < limit; k += blockDim.x)
        if (w[2 * k + 1] != 0u) s_any = 1;
    __syncthreads();
    if (threadIdx.x == 0) g_is64 = (s_any == 0) ? 1 : 0;
}

// --- fused: blocks [0,hb) -> node projection (no deg needed),
//            blocks [hb,..) -> degree reds ---
__global__ void k_deg_node(const float* __restrict__ x,
                           const float* __restrict__ W,
                           const float* __restrict__ lam,
                           const void* __restrict__ dstv,
                           int E, int N, int H, int hb) {
    if ((int)blockIdx.x < hb) {
        // ---- node path: fold weights locally, compute XA + unscaled U ----
        __shared__ float sM0[32], sM1[32], sM2[32];
        if (threadIdx.x < 32) {
            int j = threadIdx.x >> 1, o = threadIdx.x & 1;
            float r = 2.0f / __ldg(lam);
            float A = __ldg(W + o * 48 + j);
            float B = __ldg(W + o * 48 + 16 + j);
            float C = __ldg(W + o * 48 + 32 + j);
            float rm1 = r - 1.0f;
            sM0[threadIdx.x] = A + rm1 * B + (2.0f * rm1 * rm1 - 1.0f) * C;
            sM1[threadIdx.x] = -r * B - 4.0f * r * rm1 * C;
            sM2[threadIdx.x] = 2.0f * r * r * C;
        }
        __syncthreads();
        int t = blockIdx.x * blockDim.x + threadIdx.x;
        if (t >= H) return;
#pragma unroll
        for (int half = 0; half < 2; half++) {
            int i = t + half * H;
            if (i >= N) break;
            float4 xv[4];
            const float4* xr = (const float4*)(x + (size_t)i * IN_FEATS);
#pragma unroll
            for (int q = 0; q < 4; q++) xv[q] = __ldg(xr + q);
            float u0 = 0.f, u1 = 0.f, u2 = 0.f, u3 = 0.f, a0 = 0.f, a1 = 0.f;
#pragma unroll
            for (int q = 0; q < 4; q++) {
                float vals[4] = {xv[q].x, xv[q].y, xv[q].z, xv[q].w};
#pragma unroll
                for (int tt = 0; tt < 4; tt++) {
                    int j = q * 4 + tt;
                    float xj = vals[tt];
                    a0 += xj * sM0[2 * j];  a1 += xj * sM0[2 * j + 1];
                    u0 += xj * sM1[2 * j];  u1 += xj * sM1[2 * j + 1];
                    u2 += xj * sM2[2 * j];  u3 += xj * sM2[2 * j + 1];
                }
            }
            g_Us[i] = make_float4(u0, u1, u2, u3);   // unscaled
            g_XA[i] = make_float2(a0, a1);
        }
    } else {
        // ---- degree path: vectorized dst reads, grid-stride ----
        int tid = (blockIdx.x - hb) * blockDim.x + threadIdx.x;
        int S = (gridDim.x - hb) * blockDim.x;
        int P = E >> 2;
        if (g_is64) {
            const longlong2* p = (const longlong2*)dstv;
            for (int g = tid; g < P; g += S) {
                longlong2 a = __ldcs(p + 2 * g);
                longlong2 b = __ldcs(p + 2 * g + 1);
                atomicAdd(&g_deg[(int)a.x], 1); atomicAdd(&g_deg[(int)a.y], 1);
                atomicAdd(&g_deg[(int)b.x], 1); atomicAdd(&g_deg[(int)b.y], 1);
            }
            if (tid < (E & 3)) {
                int e = (P << 2) + tid;
                atomicAdd(&g_deg[(int)__ldcs((const long long*)dstv + e)], 1);
            }
        } else {
            const int4* p = (const int4*)dstv;
            for (int g = tid; g < P; g += S) {
                int4 a = __ldcs(p + g);
                atomicAdd(&g_deg[a.x], 1); atomicAdd(&g_deg[a.y], 1);
                atomicAdd(&g_deg[a.z], 1); atomicAdd(&g_deg[a.w], 1);
            }
            if (tid < (E & 3)) {
                int e = (P << 2) + tid;
                atomicAdd(&g_deg[__ldcs((const int*)dstv + e)], 1);
            }
        }
    }
}

// --- norm + scale Us; zero g_deg for next replay ---
__global__ void k_norm(int N) {
    int i = blockIdx.x * blockDim.x + threadIdx.x;
    if (i >= N) return;
    int d = g_deg[i];
    g_deg[i] = 0;
    float nrm = rsqrtf((float)max(d, 1));
    g_norm[i] = nrm;
    float4 u = g_Us[i];
    g_Us[i] = make_float4(u.x * nrm, u.y * nrm, u.z * nrm, u.w * nrm);
}

__device__ __forceinline__ int ld_idx(const void* p, int e, int is64) {
    return is64 ? (int)__ldcs((const long long*)p + e)
                : __ldcs((const int*)p + e);
}

// --- propagation pass 1: Vacc[dst] += Us[src] ---
template <bool EXACT>
__global__ void k_prop1(const void* __restrict__ srcv,
                        const void* __restrict__ dstv, int E) {
    int tid = blockIdx.x * blockDim.x + threadIdx.x;
    int S = gridDim.x * blockDim.x;
    int is64 = g_is64;
    int s[UNROLL], d[UNROLL]; bool v[UNROLL];
    float4 u[UNROLL];
#pragma unroll
    for (int j = 0; j < UNROLL; j++) {
        int e = tid + j * S;
        v[j] = EXACT || (e < E);
        int ee = v[j] ? e : 0;
        s[j] = ld_idx(srcv, ee, is64);
        d[j] = ld_idx(dstv, ee, is64);
    }
#pragma unroll
    for (int j = 0; j < UNROLL; j++)
        u[j] = __ldg(&g_Us[s[j]]);
#pragma unroll
    for (int j = 0; j < UNROLL; j++)
        if (v[j]) atomicAdd(&g_Vacc[d[j]], u[j]);
}

// --- finalize pass 1: Zs = norm²·(M2 part) ---
__global__ void k_fin1(int N) {
    int i = blockIdx.x * blockDim.x + threadIdx.x;
    if (i >= N) return;
    float nrm = g_norm[i];
    float4 vv = g_Vacc[i];
    float n2 = nrm * nrm;
    g_Zs[i] = make_float2(vv.z * n2, vv.w * n2);
}

// --- propagation pass 2: Tacc[dst] += Zs[src] ---
template <bool EXACT>
__global__ void k_prop2(const void* __restrict__ srcv,
                        const void* __restrict__ dstv, int E) {
    int tid = blockIdx.x * blockDim.x + threadIdx.x;
    int S = gridDim.x * blockDim.x;
    int is64 = g_is64;
    int s[UNROLL], d[UNROLL]; bool v[UNROLL];
    float2 z[UNROLL];
#pragma unroll
    for (int j = 0; j < UNROLL; j++) {
        int e = tid + j * S;
        v[j] = EXACT || (e < E);
        int ee = v[j] ? e : 0;
        s[j] = ld_idx(srcv, ee, is64);
        d[j] = ld_idx(dstv, ee, is64);
    }
#pragma unroll
    for (int j = 0; j < UNROLL; j++)
        z[j] = __ldg(&g_Zs[s[j]]);
#pragma unroll
    for (int j = 0; j < UNROLL; j++)
        if (v[j]) atomicAdd(&g_Tacc[d[j]], z[j]);
}

// --- epilogue: h = relu(XA + nrm·Vacc.xy + nrm·Tacc); zero accs for replay ---
__global__ void k_out(float2* __restrict__ out, int N) {
    int i = blockIdx.x * blockDim.x + threadIdx.x;
    if (i >= N) return;
    float nrm = g_norm[i];
    float4 vv = g_Vacc[i];
    float2 t = g_Tacc[i], a = g_XA[i];
    g_Vacc[i] = make_float4(0.f, 0.f, 0.f, 0.f);
    g_Tacc[i] = make_float2(0.f, 0.f);
    out[i] = make_float2(fmaxf(a.x + (vv.x + t.x) * nrm, 0.0f),
                         fmaxf(a.y + (vv.y + t.y) * nrm, 0.0f));
}

extern "C" void kernel_launch(void* const* d_in, const int* in_sizes, int n_in,
                              void* d_out, int out_size) {
    const float* in_feat = (const float*)d_in[0];
    const float* W       = (const float*)d_in[1];
    const void*  src     = d_in[2];
    const void*  dst     = d_in[3];
    const float* lam     = (const float*)d_in[4];

    int N = in_sizes[0] / IN_FEATS;
    int E = in_sizes[2];
    const int TB = 256;
    int nb  = (N + TB - 1) / TB;
    int H   = (N + 1) / 2;
    int hb  = (H + TB - 1) / TB;
    int dgb = 2048;                       // deg grid-stride blocks
    int eb4 = (E + TB * UNROLL - 1) / (TB * UNROLL);
    bool exact = (E % (TB * UNROLL)) == 0;

    k_detect<<<1, 256>>>((const unsigned*)src, E);
    k_deg_node<<<hb + dgb, TB>>>(in_feat, W, lam, dst, E, N, H, hb);
    k_norm<<<nb, TB>>>(N);
    if (exact) k_prop1<true><<<eb4, TB>>>(src, dst, E);
    else       k_prop1<false><<<eb4, TB>>>(src, dst, E);
    k_fin1<<<nb, TB>>>(N);
    if (exact) k_prop2<true><<<eb4, TB>>>(src, dst, E);
    else       k_prop2<false><<<eb4, TB>>>(src, dst, E);
    k_out<<<nb, TB>>>((float2*)d_out, N);
}